// round 16
// baseline (speedup 1.0000x reference)
#include <cuda_runtime.h>
#include <cuda_fp16.h>
#include <math.h>
#include <stdint.h>

#define TSTEPS 12
#define BATCH  8

#define LSCALE 1024.0f
#define LINV   (1.0f / 1024.0f)

// ---------------- scratch (static device globals) ---------------------------
__device__ float  g_seq1[(size_t)TSTEPS * BATCH * 64 * 64 * 64];
__device__ float  g_seq2[(size_t)TSTEPS * BATCH * 128 * 32 * 32];
__device__ float  g_h3a [(size_t)BATCH * 128 * 16 * 16];
__device__ float  g_h3b [(size_t)BATCH * 128 * 16 * 16];
// fp16 H/L activations: uint4 per 4-CHANNEL GROUP per pixel:
//  channel c: plane = (c>>4)*4 + ((c&7)>>1); half idx = ((c>>3)&1)*2 + (c&1)
//  (.x,.y) = H halves (k-rows 0..7, 8..15);  (.z,.w) = L halves * 1024
__device__ uint4  g_xsp1[(size_t)TSTEPS * BATCH * 16 * 64 * 64];
__device__ uint4  g_xsp2[(size_t)TSTEPS * BATCH * 32 * 32 * 32];
__device__ uint4  g_xsp3[(size_t)TSTEPS * BATCH * 32 * 16 * 16];
__device__ uint4  g_hsp1a[(size_t)BATCH * 16 * 64 * 64];
__device__ uint4  g_hsp1b[(size_t)BATCH * 16 * 64 * 64];
__device__ uint4  g_hsp2a[(size_t)BATCH * 32 * 32 * 32];
__device__ uint4  g_hsp2b[(size_t)BATCH * 32 * 32 * 32];
__device__ uint4  g_hsp3a[(size_t)BATCH * 32 * 16 * 16];
__device__ uint4  g_hsp3b[(size_t)BATCH * 32 * 16 * 16];
__device__ uint4  g_rhsp[(size_t)BATCH * 16 * 64 * 64];
__device__ uint4  g_zsp [(size_t)BATCH * 16 * 64 * 64];
__device__ float  g_zr  [(size_t)BATCH * 128 * 64 * 64];
__device__ float  g_part[(size_t)8388608];
__device__ float  g_zero[(size_t)BATCH * 64 * 64 * 64];
// fp16-pair weights: per conv, H array then L array (L pre-scaled x1024).
__device__ uint32_t g_wcvt[(size_t)5529600];

// ---------------- fp16 helpers ----------------------------------------------
__device__ __forceinline__ uint16_t f2h(float v) {
    return __half_as_ushort(__float2half_rn(v));
}
__device__ __forceinline__ float h2f(uint16_t u) {
    return __half2float(__ushort_as_half(u));
}
__device__ __forceinline__ void storeSplit(uint4* planeBase, int c, long long HW,
                                           long long pix, float v) {
    uint16_t* p = (uint16_t*)(planeBase
        + (long long)((c >> 4) * 4 + ((c & 7) >> 1)) * HW + pix);
    int idx = ((c >> 3) & 1) * 2 + (c & 1);
    uint16_t hb = f2h(v);
    p[idx]     = hb;
    p[4 + idx] = f2h((v - h2f(hb)) * LSCALE);
}
__device__ __forceinline__ float loadSplit(const uint4* planeBase, int c, long long HW,
                                           long long pix) {
    const uint16_t* p = (const uint16_t*)(planeBase
        + (long long)((c >> 4) * 4 + ((c & 7) >> 1)) * HW + pix);
    int idx = ((c >> 3) & 1) * 2 + (c & 1);
    return h2f(p[idx]) + h2f(p[4 + idx]) * LINV;
}

__global__ void zerok(float* p, uint4* p2, int n, int n2) {
    int i = blockIdx.x * blockDim.x + threadIdx.x;
    if (i < n) p[i] = 0.0f;
    if (i < n2) p2[i] = make_uint4(0, 0, 0, 0);
}
__global__ void copyk(float* __restrict__ dst, const float* __restrict__ src, int n) {
    int i = blockIdx.x * blockDim.x + threadIdx.x;
    if (i < n) dst[i] = src[i];
}
// weight conversion: fp32 [oc][Cin][25] -> H and L*1024 fp16-pair words [oc][Cin/2][25]
__global__ void wcvt2K(const float* __restrict__ w, uint32_t* __restrict__ oH,
                       uint32_t* __restrict__ oL, int n, int CinHalf) {
    int i = blockIdx.x * blockDim.x + threadIdx.x;
    if (i >= n) return;
    int khkw = i % 25;
    int icp  = (i / 25) % CinHalf;
    int oc   = i / (25 * CinHalf);
    float w0 = w[((long long)(oc * 2 * CinHalf + 2 * icp)) * 25 + khkw];
    float w1 = w[((long long)(oc * 2 * CinHalf + 2 * icp + 1)) * 25 + khkw];
    uint16_t h0 = f2h(w0);
    uint16_t h1 = f2h(w1);
    uint16_t l0 = f2h((w0 - h2f(h0)) * LSCALE);
    uint16_t l1 = f2h((w1 - h2f(h1)) * LSCALE);
    oH[i] = ((uint32_t)h1 << 16) | h0;
    oL[i] = ((uint32_t)l1 << 16) | l0;
}

// ---------------- cp.async helpers ------------------------------------------
__device__ __forceinline__ void cp4(uint32_t saddr, const void* g, bool ok) {
    int sz = ok ? 4 : 0;
    asm volatile("cp.async.ca.shared.global [%0], [%1], 4, %2;\n"
                 :: "r"(saddr), "l"(g), "r"(sz));
}
__device__ __forceinline__ void cp8(uint32_t saddr, const void* g, bool ok) {
    int sz = ok ? 8 : 0;
    asm volatile("cp.async.ca.shared.global [%0], [%1], 8, %2;\n"
                 :: "r"(saddr), "l"(g), "r"(sz));
}
__device__ __forceinline__ void cpCommit() {
    asm volatile("cp.async.commit_group;\n" ::: "memory");
}
template <int N>
__device__ __forceinline__ void cpWait() {
    asm volatile("cp.async.wait_group %0;\n" :: "n"(N) : "memory");
}
__device__ __forceinline__ void mma16h(float* d, uint32_t a0, uint32_t a1, uint32_t a2,
                                       uint32_t a3, uint32_t b0, uint32_t b1) {
    asm volatile(
        "mma.sync.aligned.m16n8k16.row.col.f32.f16.f16.f32 "
        "{%0,%1,%2,%3}, {%4,%5,%6,%7}, {%8,%9}, {%0,%1,%2,%3};"
        : "+f"(d[0]), "+f"(d[1]), "+f"(d[2]), "+f"(d[3])
        : "r"(a0), "r"(a1), "r"(a2), "r"(a3), "r"(b0), "r"(b1));
}

// ---------------------------------------------------------------------------
// Strided conv k4 s2 p1, batched over T. Output written H/L uint4 plane format.
// OC = 16: each thread writes 4 complete uint4 plane entries.
// ---------------------------------------------------------------------------
template <int TX, int TY, int OC>
__global__ void conv4s2(const float* __restrict__ in,
                        long long strideB, long long strideT,
                        const float* __restrict__ w, const float* __restrict__ bias,
                        uint4* __restrict__ out,
                        int Cin, int Cout, int Hin, int Win)
{
    const int Hout = Hin >> 1, Wout = Win >> 1;
    const int ocG = Cout / OC;
    int z = blockIdx.z;
    const int ocb = z % ocG; z /= ocG;
    const int b   = z % BATCH;
    const int t   = z / BATCH;
    const int y0  = blockIdx.y * TY;
    const int x0  = blockIdx.x * TX;

    constexpr int IW = 2 * TX + 2;
    constexpr int IH = 2 * TY + 2;
    __shared__ float s_in[IH * IW];
    __shared__ float s_w[OC * 16];

    const int tid = threadIdx.y * TX + threadIdx.x;
    const int nth = TX * TY;
    const float* base = in + (long long)b * strideB + (long long)t * strideT;

    float acc[OC];
#pragma unroll
    for (int oc = 0; oc < OC; oc++) acc[oc] = 0.0f;

    for (int ic = 0; ic < Cin; ic++) {
        const float* src = base + (long long)ic * Hin * Win;
        for (int idx = tid; idx < IH * IW; idx += nth) {
            int iy = 2 * y0 - 1 + idx / IW;
            int ix = 2 * x0 - 1 + idx % IW;
            s_in[idx] = (iy >= 0 && iy < Hin && ix >= 0 && ix < Win)
                            ? src[(long long)iy * Win + ix] : 0.0f;
        }
        for (int idx = tid; idx < OC * 16; idx += nth) {
            int oc = idx / 16, k = idx % 16;
            s_w[idx] = w[(((long long)(ocb * OC + oc)) * Cin + ic) * 16 + k];
        }
        __syncthreads();
#pragma unroll
        for (int kh = 0; kh < 4; kh++)
#pragma unroll
            for (int kw = 0; kw < 4; kw++) {
                float inv = s_in[(2 * threadIdx.y + kh) * IW + 2 * threadIdx.x + kw];
#pragma unroll
                for (int oc = 0; oc < OC; oc++)
                    acc[oc] = fmaf(inv, s_w[oc * 16 + kh * 4 + kw], acc[oc]);
            }
        __syncthreads();
    }

    const int y = y0 + threadIdx.y, x = x0 + threadIdx.x;
    const long long HWo = (long long)Hout * Wout;
    uint4* ob = out + (long long)(t * BATCH + b) * (Cout >> 2) * HWo;
#pragma unroll
    for (int p = 0; p < 4; p++) {
        float v0 = acc[2 * p]         + bias[ocb * 16 + 2 * p];
        float v1 = acc[2 * p + 1]     + bias[ocb * 16 + 2 * p + 1];
        float v2 = acc[8 + 2 * p]     + bias[ocb * 16 + 8 + 2 * p];
        float v3 = acc[8 + 2 * p + 1] + bias[ocb * 16 + 8 + 2 * p + 1];
        uint16_t h0 = f2h(v0), h1 = f2h(v1), h2 = f2h(v2), h3 = f2h(v3);
        uint16_t l0 = f2h((v0 - h2f(h0)) * LSCALE);
        uint16_t l1 = f2h((v1 - h2f(h1)) * LSCALE);
        uint16_t l2 = f2h((v2 - h2f(h2)) * LSCALE);
        uint16_t l3 = f2h((v3 - h2f(h3)) * LSCALE);
        ob[(long long)(ocb * 4 + p) * HWo + (long long)y * Wout + x]
            = make_uint4(((uint32_t)h1 << 16) | h0, ((uint32_t)h3 << 16) | h2,
                         ((uint32_t)l1 << 16) | l0, ((uint32_t)l3 << 16) | l2);
    }
}

// ---------------------------------------------------------------------------
// 5x5 conv s1 p2, implicit GEMM, fp16 mma.sync.m16n8k16, 3-MMA corrected:
//   accH += wH*bH;  accL += (wL*1024)*bH;  accL += wH*(bL*1024)
//   result = accH + accL/1024  (only second-order wL*bL dropped).
// K=16 REAL input channels per MMA trio. Block 128 thr, 16 oc, TX x 8 px.
// smem: input [2buf][4H + 4L planes][SPAD] uint2; weights [2buf][25][2HL][16oc][8].
// EPI 0: fused sigmoid -> zr fp32 + rh split (KS must be 1). EPI 2: raw partial.
// blockIdx.z = ((b*ocG + ocb)*KS + ks)
// ---------------------------------------------------------------------------
template <int TX, int EPI>
__global__ void __launch_bounds__(128)
conv5hf(const uint4* __restrict__ src0, int C0,
        const uint4* __restrict__ src1, int C1,
        const uint32_t* __restrict__ wH, const uint32_t* __restrict__ wL,
        const float* __restrict__ bias,
        float* __restrict__ out, uint4* __restrict__ rhOut,
        int Cout, int H, int W, int ocG, int KS, int chunkIC)
{
    constexpr int TY = 8, IW = TX + 4, IH = TY + 4, IN = IH * IW;
    constexpr int SPAD = IN + ((4 - (IN % 16) + 16) % 16);  // SPAD % 16 == 4
    constexpr int PB = TX / 8;
    constexpr int NG = 2 * PB;
    constexpr int WN = 25 * 256;                             // 6400 u32 per buf

    extern __shared__ uint32_t smu[];
    uint2*    s_in = (uint2*)smu;          // [2][8][SPAD] uint2 (planes 0-3 H, 4-7 L)
    uint32_t* s_w  = smu + 32 * SPAD;      // [2][WN]

    int z = blockIdx.z;
    const int ks  = z % KS;  z /= KS;
    const int ocb = z % ocG;
    const int b   = z / ocG;
    const int y0  = blockIdx.y * TY;
    const int x0  = blockIdx.x * TX;
    const int tid  = threadIdx.x;
    const int warp = tid >> 5, lane = tid & 31;
    const int gid  = lane >> 2, tig = lane & 3;

    const int Cin = C0 + C1;
    const long long HW = (long long)H * W;
    const int icBeg = ks * chunkIC;
    const int NC = chunkIC / 16;            // 16 real channels per chunk

    const uint32_t sIN = (uint32_t)__cvta_generic_to_shared(s_in);
    const uint32_t sWB = (uint32_t)__cvta_generic_to_shared(s_w);

    auto fillChunk = [&](int buf, int ck) {
        const int cs = icBeg + ck * 16;  // chunks never straddle the C0 boundary
        const uint4* pb = (cs < C0)
            ? src0 + ((long long)b * (C0 >> 2) + (cs >> 2)) * HW
            : src1 + ((long long)b * (C1 >> 2) + ((cs - C0) >> 2)) * HW;
        for (int idx = tid; idx < IN; idx += 128) {
            int rr = idx / IW, cc = idx - rr * IW;
            int iy = y0 - 2 + rr, ix = x0 - 2 + cc;
            bool ok = (iy >= 0) && (iy < H) && (ix >= 0) && (ix < W);
            const uint4* g = ok ? (pb + (long long)iy * W + ix) : pb;
            uint32_t dH = sIN + (uint32_t)(buf * 8 * SPAD + idx) * 8u;
            uint32_t dL = dH + (uint32_t)(4 * SPAD) * 8u;
#pragma unroll
            for (int t = 0; t < 4; t++) {
                const char* gp = (const char*)(g + (long long)t * HW);
                cp8(dH + (uint32_t)(t * SPAD) * 8u, gp, ok);       // H pair
                cp8(dL + (uint32_t)(t * SPAD) * 8u, gp + 8, ok);   // L pair
            }
        }
        for (int idx = tid; idx < WN; idx += 128) {
            // idx = khkw*256 + half*128 + oc*8 + e ; e=2p+j -> kpair = p + 4j
            int khkw = idx >> 8;
            int rem  = idx & 255;
            int half = rem >> 7;
            int r2   = rem & 127;
            int oc   = r2 >> 3;
            int e    = r2 & 7;
            int kp   = (e >> 1) + 4 * (e & 1);
            int icp  = (cs >> 1) + kp;
            const uint32_t* g = (half ? wL : wH)
                + ((long long)(ocb * 16 + oc) * (Cin >> 1) + icp) * 25 + khkw;
            cp4(sWB + (uint32_t)(buf * WN + idx) * 4u, g, true);
        }
    };

    float accH[NG][4], accL[NG][4];
#pragma unroll
    for (int g = 0; g < NG; g++)
#pragma unroll
        for (int j = 0; j < 4; j++) { accH[g][j] = 0.0f; accL[g][j] = 0.0f; }

    fillChunk(0, 0);
    cpCommit();

    for (int ck = 0; ck < NC; ck++) {
        const int cur = ck & 1;
        if (ck + 1 < NC) fillChunk(cur ^ 1, ck + 1);
        cpCommit();
        cpWait<1>();
        __syncthreads();

        const uint2*    siTH = s_in + cur * 8 * SPAD + tig * SPAD;
        const uint2*    siTL = siTH + 4 * SPAD;
        const uint32_t* swB  = s_w + cur * WN;
        const int prow = 2 * warp;

#pragma unroll
        for (int kh = 0; kh < 5; kh++) {
#pragma unroll
            for (int kw = 0; kw < 5; kw++) {
                const uint32_t* swk = swB + (kh * 5 + kw) * 256;
                uint2 h02 = *(const uint2*)(swk + gid * 8 + tig * 2);
                uint2 h13 = *(const uint2*)(swk + (gid + 8) * 8 + tig * 2);
                uint2 l02 = *(const uint2*)(swk + 128 + gid * 8 + tig * 2);
                uint2 l13 = *(const uint2*)(swk + 128 + (gid + 8) * 8 + tig * 2);
#pragma unroll
                for (int g = 0; g < NG; g++) {
                    const int r = g / PB, pb2 = g % PB;
                    const int px = (prow + r + kh) * IW + 8 * pb2 + gid + kw;
                    uint2 bH = siTH[px];
                    uint2 bL = siTL[px];
                    mma16h(accH[g], h02.x, h13.x, h02.y, h13.y, bH.x, bH.y);
                    mma16h(accL[g], l02.x, l13.x, l02.y, l13.y, bH.x, bH.y);
                    mma16h(accL[g], h02.x, h13.x, h02.y, h13.y, bL.x, bL.y);
                }
            }
        }
        __syncthreads();
    }

    // epilogue: v = accH + accL/1024
#pragma unroll
    for (int g = 0; g < NG; g++) {
        const int r = g / PB, pb2 = g % PB;
        const int y = y0 + 2 * warp + r;
        const int xb = x0 + 8 * pb2 + 2 * tig;
#pragma unroll
        for (int j = 0; j < 4; j++) {
            const int m = gid + ((j >> 1) << 3);
            const int x = xb + (j & 1);
            const int c = ocb * 16 + m;
            const long long pix = (long long)y * W + x;
            float v = accH[g][j] + accL[g][j] * LINV;
            if (EPI == 0) {
                float a = v + bias[c];
                float s = 1.0f / (1.0f + expf(-a));
                out[((long long)b * Cout + c) * HW + pix] = s;
                const int Ch = Cout >> 1;
                if (c >= Ch) {
                    int hc = c - Ch;
                    const uint4* hp = src1 + (long long)b * (C1 >> 2) * HW;
                    float hv = loadSplit(hp, hc, HW, pix);
                    uint4* rp = rhOut + (long long)b * (C1 >> 2) * HW;
                    storeSplit(rp, hc, HW, pix, s * hv);
                }
            } else {
                out[((long long)(ks * BATCH + b) * Cout + c) * HW + pix] = v;
            }
        }
    }
}

// ---------------------------------------------------------------------------
// Split-K epilogues
// ---------------------------------------------------------------------------
__global__ void zrEpiK(const float* __restrict__ part, int KS,
                       const float* __restrict__ bias, const float* __restrict__ hprevFp,
                       float* __restrict__ zrOut, uint4* __restrict__ rhSp,
                       int C2, long long HW)
{
    const long long n = (long long)BATCH * C2 * HW;
    long long i = (long long)blockIdx.x * blockDim.x + threadIdx.x;
    if (i >= n) return;
    float s = 0.0f;
    for (int k = 0; k < KS; k++) s += part[(long long)k * n + i];
    const int c = (int)((i / HW) % C2);
    s += bias[c];
    float sg = 1.0f / (1.0f + expf(-s));
    zrOut[i] = sg;
    const int C = C2 >> 1;
    if (c >= C) {
        long long b = i / (HW * C2);
        long long pix = i % HW;
        int hc = c - C;
        float rv = sg * hprevFp[(b * C + hc) * HW + pix];
        storeSplit(rhSp + b * (C >> 2) * HW, hc, HW, pix, rv);
    }
}

__global__ void hEpiK(const float* __restrict__ part, int KS,
                      const float* __restrict__ bias, const float* __restrict__ zr,
                      const float* __restrict__ hprevFp,
                      float* __restrict__ outFp, uint4* __restrict__ outSp,
                      int C, long long HW)
{
    const long long n = (long long)BATCH * C * HW;
    long long i = (long long)blockIdx.x * blockDim.x + threadIdx.x;
    if (i >= n) return;
    float s = 0.0f;
    for (int k = 0; k < KS; k++) s += part[(long long)k * n + i];
    const int c = (int)((i / HW) % C);
    long long b = i / (HW * C);
    long long pix = i % HW;
    float a = s + bias[c];
    float zv = zr[(b * (2 * C) + c) * HW + pix];
    float hp = hprevFp[i];
    float res = (1.0f - zv) * hp + zv * tanhf(a);
    outFp[i] = res;
    storeSplit(outSp + b * (C >> 2) * HW, c, HW, pix, res);
}

// ---------------------------------------------------------------------------

extern "C" void kernel_launch(void* const* d_in, const int* in_sizes, int n_in,
                              void* d_out, int out_size)
{
    const float* input   = (const float*)d_in[0];
    const float* c1_w    = (const float*)d_in[1];
    const float* c1_b    = (const float*)d_in[2];
    const float* g1_zr_w = (const float*)d_in[3];
    const float* g1_zr_b = (const float*)d_in[4];
    const float* g1_h_w  = (const float*)d_in[5];
    const float* g1_h_b  = (const float*)d_in[6];
    const float* c2_w    = (const float*)d_in[7];
    const float* c2_b    = (const float*)d_in[8];
    const float* g2_zr_w = (const float*)d_in[9];
    const float* g2_zr_b = (const float*)d_in[10];
    const float* g2_h_w  = (const float*)d_in[11];
    const float* g2_h_b  = (const float*)d_in[12];
    const float* c3_w    = (const float*)d_in[13];
    const float* c3_b    = (const float*)d_in[14];
    const float* g3_zr_w = (const float*)d_in[15];
    const float* g3_zr_b = (const float*)d_in[16];
    const float* g3_h_w  = (const float*)d_in[17];
    const float* g3_h_b  = (const float*)d_in[18];

    float *seq1, *seq2, *h3a, *h3b, *zr, *part, *zero0;
    uint4 *xsp1, *xsp2, *xsp3, *hsp1a, *hsp1b, *hsp2a, *hsp2b, *hsp3a, *hsp3b, *rhsp, *zsp;
    uint32_t* wc;
    cudaGetSymbolAddress((void**)&seq1,  g_seq1);
    cudaGetSymbolAddress((void**)&seq2,  g_seq2);
    cudaGetSymbolAddress((void**)&h3a,   g_h3a);
    cudaGetSymbolAddress((void**)&h3b,   g_h3b);
    cudaGetSymbolAddress((void**)&xsp1,  g_xsp1);
    cudaGetSymbolAddress((void**)&xsp2,  g_xsp2);
    cudaGetSymbolAddress((void**)&xsp3,  g_xsp3);
    cudaGetSymbolAddress((void**)&hsp1a, g_hsp1a);
    cudaGetSymbolAddress((void**)&hsp1b, g_hsp1b);
    cudaGetSymbolAddress((void**)&hsp2a, g_hsp2a);
    cudaGetSymbolAddress((void**)&hsp2b, g_hsp2b);
    cudaGetSymbolAddress((void**)&hsp3a, g_hsp3a);
    cudaGetSymbolAddress((void**)&hsp3b, g_hsp3b);
    cudaGetSymbolAddress((void**)&rhsp,  g_rhsp);
    cudaGetSymbolAddress((void**)&zr,    g_zr);
    cudaGetSymbolAddress((void**)&part,  g_part);
    cudaGetSymbolAddress((void**)&zero0, g_zero);
    cudaGetSymbolAddress((void**)&zsp,   g_zsp);
    cudaGetSymbolAddress((void**)&wc,    g_wcvt);

    // converted-weight offsets: per conv, H then L (each Noc*Cin/2*25 words)
    uint32_t* w1zrH = wc;                  // 128*64*25  = 204800
    uint32_t* w1zrL = wc + 204800;
    uint32_t* w1hH  = wc + 409600;         //  64*64*25  = 102400
    uint32_t* w1hL  = wc + 512000;
    uint32_t* w2zrH = wc + 614400;         // 256*128*25 = 819200
    uint32_t* w2zrL = wc + 1433600;
    uint32_t* w2hH  = wc + 2252800;        // 128*128*25 = 409600
    uint32_t* w2hL  = wc + 2662400;
    uint32_t* w3zrH = wc + 3072000;        // 819200
    uint32_t* w3zrL = wc + 3891200;
    uint32_t* w3hH  = wc + 4710400;        // 409600
    uint32_t* w3hL  = wc + 5120000;

    // smem sizes: input [2][8][SPAD] uint2 + weights [2][6400] u32
    constexpr int IN32 = 12 * 36, SP32 = IN32 + ((4 - (IN32 % 16) + 16) % 16); // 436
    constexpr int IN16 = 12 * 20, SP16 = IN16 + ((4 - (IN16 % 16) + 16) % 16); // 244
    constexpr int WN2  = 2 * 25 * 256;                                          // 12800 u32
    constexpr int SM32 = (32 * SP32 + WN2) * 4;   // 107,008 B -> 2 blocks/SM
    constexpr int SM16 = (32 * SP16 + WN2) * 4;   //  82,432 B -> 2 blocks/SM
    cudaFuncSetAttribute(conv5hf<32, 0>, cudaFuncAttributeMaxDynamicSharedMemorySize, SM32);
    cudaFuncSetAttribute(conv5hf<32, 2>, cudaFuncAttributeMaxDynamicSharedMemorySize, SM32);
    cudaFuncSetAttribute(conv5hf<16, 2>, cudaFuncAttributeMaxDynamicSharedMemorySize, SM16);

    {   // zero h0 buffers (fp32 + uint4 planes)
        int nz = BATCH * 64 * 64 * 64;
        int nz2 = BATCH * 16 * 64 * 64;
        zerok<<<(nz + 255) / 256, 256>>>(zero0, zsp, nz, nz2);
    }

    const size_t S1  = (size_t)BATCH * 64 * 64 * 64;
    const size_t S2  = (size_t)BATCH * 128 * 32 * 32;
    const size_t S1p = (size_t)BATCH * 16 * 64 * 64;
    const size_t S2p = (size_t)BATCH * 32 * 32 * 32;
    const size_t S3p = (size_t)BATCH * 32 * 16 * 16;

    // ================= Stage 1: 1 -> 64ch, 128x128 -> 64x64 =================
    conv4s2<16, 8, 16><<<dim3(4, 8, TSTEPS * BATCH * 4), dim3(16, 8)>>>(
        input, (long long)TSTEPS * 128 * 128, (long long)128 * 128,
        c1_w, c1_b, xsp1, 1, 64, 128, 128);

    wcvt2K<<<(204800 + 255) / 256, 256>>>(g1_zr_w, w1zrH, w1zrL, 204800, 64);
    wcvt2K<<<(102400 + 255) / 256, 256>>>(g1_h_w,  w1hH,  w1hL,  102400, 64);

    {
        uint4* hspb[2] = { hsp1a, hsp1b };
        for (int t = 0; t < TSTEPS; t++) {
            const uint4* xt = xsp1 + (size_t)t * S1p;
            const uint4* hprevSp = t ? hspb[(t - 1) & 1] : zsp;
            const float* hprevFp = t ? seq1 + (size_t)(t - 1) * S1 : zero0;
            // zr fused (KS=1): Cout=128, ocG=8
            conv5hf<32, 0><<<dim3(2, 8, BATCH * 8), 128, SM32>>>(
                xt, 64, hprevSp, 64, w1zrH, w1zrL, g1_zr_b, zr, rhsp, 128, 64, 64, 8, 1, 128);
            // h raw split-K=2: Cout=64, ocG=4
            conv5hf<32, 2><<<dim3(2, 8, BATCH * 4 * 2), 128, SM32>>>(
                xt, 64, rhsp, 64, w1hH, w1hL, nullptr, part, nullptr, 64, 64, 64, 4, 2, 64);
            long long n = (long long)BATCH * 64 * 4096;
            hEpiK<<<(unsigned)((n + 255) / 256), 256>>>(
                part, 2, g1_h_b, zr, hprevFp, seq1 + (size_t)t * S1, hspb[t & 1], 64, 4096);
        }
    }

    // stage-2/3 weight conversions (needed before stage 2)
    wcvt2K<<<(819200 + 255) / 256, 256>>>(g2_zr_w, w2zrH, w2zrL, 819200, 128);
    wcvt2K<<<(409600 + 255) / 256, 256>>>(g2_h_w,  w2hH,  w2hL,  409600, 128);
    wcvt2K<<<(819200 + 255) / 256, 256>>>(g3_zr_w, w3zrH, w3zrL, 819200, 128);
    wcvt2K<<<(409600 + 255) / 256, 256>>>(g3_h_w,  w3hH,  w3hL,  409600, 128);

    // ================= Stage 2: 64 -> 128ch, 64x64 -> 32x32 =================
    conv4s2<16, 8, 16><<<dim3(2, 4, TSTEPS * BATCH * 8), dim3(16, 8)>>>(
        seq1, (long long)64 * 4096, (long long)BATCH * 64 * 4096,
        c2_w, c2_b, xsp2, 64, 128, 64, 64);

    {
        uint4* hspb[2] = { hsp2a, hsp2b };
        for (int t = 0; t < TSTEPS; t++) {
            const uint4* xt = xsp2 + (size_t)t * S2p;
            const uint4* hprevSp = t ? hspb[(t - 1) & 1] : zsp;
            const float* hprevFp = t ? seq2 + (size_t)(t - 1) * S2 : zero0;
            // zr raw split-K=2: Cout=256, ocG=16
            conv5hf<32, 2><<<dim3(1, 4, BATCH * 16 * 2), 128, SM32>>>(
                xt, 128, hprevSp, 128, w2zrH, w2zrL, nullptr, part, nullptr, 256, 32, 32, 16, 2, 128);
            {
                long long n = (long long)BATCH * 256 * 1024;
                zrEpiK<<<(unsigned)((n + 255) / 256), 256>>>(part, 2, g2_zr_b, hprevFp, zr, rhsp, 256, 1024);
            }
            // h raw split-K=4: Cout=128, ocG=8
            conv5hf<32, 2><<<dim3(1, 4, BATCH * 8 * 4), 128, SM32>>>(
                xt, 128, rhsp, 128, w2hH, w2hL, nullptr, part, nullptr, 128, 32, 32, 8, 4, 64);
            long long n = (long long)BATCH * 128 * 1024;
            hEpiK<<<(unsigned)((n + 255) / 256), 256>>>(
                part, 4, g2_h_b, zr, hprevFp, seq2 + (size_t)t * S2, hspb[t & 1], 128, 1024);
        }
    }

    // ================= Stage 3: 128 -> 128ch, 32x32 -> 16x16 ================
    conv4s2<16, 8, 16><<<dim3(1, 2, TSTEPS * BATCH * 8), dim3(16, 8)>>>(
        seq2, (long long)128 * 1024, (long long)BATCH * 128 * 1024,
        c3_w, c3_b, xsp3, 128, 128, 32, 32);

    float* h3final = nullptr;
    {
        uint4* hspb[2] = { hsp3a, hsp3b };
        float* hfp[2]  = { h3a, h3b };
        for (int t = 0; t < TSTEPS; t++) {
            const uint4* xt = xsp3 + (size_t)t * S3p;
            const uint4* hprevSp = t ? hspb[(t - 1) & 1] : zsp;
            const float* hprevFp = t ? hfp[(t - 1) & 1] : zero0;
            // zr raw split-K=4: Cout=256, ocG=16
            conv5hf<16, 2><<<dim3(1, 2, BATCH * 16 * 4), 128, SM16>>>(
                xt, 128, hprevSp, 128, w3zrH, w3zrL, nullptr, part, nullptr, 256, 16, 16, 16, 4, 64);
            {
                long long n = (long long)BATCH * 256 * 256;
                zrEpiK<<<(unsigned)((n + 255) / 256), 256>>>(part, 4, g3_zr_b, hprevFp, zr, rhsp, 256, 256);
            }
            // h raw split-K=8: Cout=128, ocG=8
            conv5hf<16, 2><<<dim3(1, 2, BATCH * 8 * 8), 128, SM16>>>(
                xt, 128, rhsp, 128, w3hH, w3hL, nullptr, part, nullptr, 128, 16, 16, 8, 8, 32);
            long long n = (long long)BATCH * 128 * 256;
            hEpiK<<<(unsigned)((n + 255) / 256), 256>>>(
                part, 8, g3_h_b, zr, hprevFp, hfp[t & 1], hspb[t & 1], 128, 256);
            h3final = hfp[t & 1];
        }
    }

    // ================= Gather outputs =================
    float* out = (float*)d_out;
    int n1 = (int)S1, n2 = (int)S2, n3 = BATCH * 128 * 16 * 16;
    copyk<<<(n1 + 255) / 256, 256>>>(out, seq1 + (size_t)(TSTEPS - 1) * S1, n1);
    copyk<<<(n2 + 255) / 256, 256>>>(out + n1, seq2 + (size_t)(TSTEPS - 1) * S2, n2);
    copyk<<<(n3 + 255) / 256, 256>>>(out + n1 + n2, h3final, n3);
}

// round 17
// speedup vs baseline: 1.0739x; 1.0739x over previous
#include <cuda_runtime.h>
#include <cuda_bf16.h>
#include <math.h>
#include <stdint.h>

#define TSTEPS 12
#define BATCH  8

// ---------------- scratch (static device globals) ---------------------------
__device__ float  g_seq1[(size_t)TSTEPS * BATCH * 64 * 64 * 64];
__device__ float  g_seq2[(size_t)TSTEPS * BATCH * 128 * 32 * 32];
__device__ float  g_h3a [(size_t)BATCH * 128 * 16 * 16];
__device__ float  g_h3b [(size_t)BATCH * 128 * 16 * 16];
// bf16 H/L activations: uint4 per 4-CHANNEL GROUP per pixel (16-ch super-groups):
//  channel c: plane = (c>>4)*4 + ((c&7)>>1); half idx = ((c>>3)&1)*2 + (c&1)
//  (.x,.y) = H halves (k-rows 0..7, 8..15);  (.z,.w) = L halves (unscaled; bf16
//  exponent range makes residuals representable without scaling)
__device__ uint4  g_xsp1[(size_t)TSTEPS * BATCH * 16 * 64 * 64];
__device__ uint4  g_xsp2[(size_t)TSTEPS * BATCH * 32 * 32 * 32];
__device__ uint4  g_xsp3[(size_t)TSTEPS * BATCH * 32 * 16 * 16];
__device__ uint4  g_hsp1a[(size_t)BATCH * 16 * 64 * 64];
__device__ uint4  g_hsp1b[(size_t)BATCH * 16 * 64 * 64];
__device__ uint4  g_hsp2a[(size_t)BATCH * 32 * 32 * 32];
__device__ uint4  g_hsp2b[(size_t)BATCH * 32 * 32 * 32];
__device__ uint4  g_hsp3a[(size_t)BATCH * 32 * 16 * 16];
__device__ uint4  g_hsp3b[(size_t)BATCH * 32 * 16 * 16];
__device__ uint4  g_rhsp[(size_t)BATCH * 16 * 64 * 64];
__device__ uint4  g_zsp [(size_t)BATCH * 16 * 64 * 64];
__device__ float  g_zr  [(size_t)BATCH * 128 * 64 * 64];
__device__ float  g_part[(size_t)8388608];
__device__ float  g_zero[(size_t)BATCH * 64 * 64 * 64];
// bf16-pair weights: per conv, H array then L array (residual, unscaled).
__device__ uint32_t g_wcvt[(size_t)5529600];

// ---------------- bf16 helpers -----------------------------------------------
__device__ __forceinline__ uint16_t b2u(float v) {
    return __bfloat16_as_ushort(__float2bfloat16(v));
}
__device__ __forceinline__ float u2b(uint16_t u) {
    return __bfloat162float(__ushort_as_bfloat16(u));
}
__device__ __forceinline__ void storeSplit(uint4* planeBase, int c, long long HW,
                                           long long pix, float v) {
    uint16_t* p = (uint16_t*)(planeBase
        + (long long)((c >> 4) * 4 + ((c & 7) >> 1)) * HW + pix);
    int idx = ((c >> 3) & 1) * 2 + (c & 1);
    uint16_t hb = b2u(v);
    p[idx]     = hb;
    p[4 + idx] = b2u(v - u2b(hb));
}
__device__ __forceinline__ float loadSplit(const uint4* planeBase, int c, long long HW,
                                           long long pix) {
    const uint16_t* p = (const uint16_t*)(planeBase
        + (long long)((c >> 4) * 4 + ((c & 7) >> 1)) * HW + pix);
    int idx = ((c >> 3) & 1) * 2 + (c & 1);
    return u2b(p[idx]) + u2b(p[4 + idx]);
}

__global__ void zerok(float* p, uint4* p2, int n, int n2) {
    int i = blockIdx.x * blockDim.x + threadIdx.x;
    if (i < n) p[i] = 0.0f;
    if (i < n2) p2[i] = make_uint4(0, 0, 0, 0);
}
__global__ void copyk(float* __restrict__ dst, const float* __restrict__ src, int n) {
    int i = blockIdx.x * blockDim.x + threadIdx.x;
    if (i < n) dst[i] = src[i];
}
// weight conversion: fp32 [oc][Cin][25] -> H and L bf16-pair words [oc][Cin/2][25]
__global__ void wcvt2K(const float* __restrict__ w, uint32_t* __restrict__ oH,
                       uint32_t* __restrict__ oL, int n, int CinHalf) {
    int i = blockIdx.x * blockDim.x + threadIdx.x;
    if (i >= n) return;
    int khkw = i % 25;
    int icp  = (i / 25) % CinHalf;
    int oc   = i / (25 * CinHalf);
    float w0 = w[((long long)(oc * 2 * CinHalf + 2 * icp)) * 25 + khkw];
    float w1 = w[((long long)(oc * 2 * CinHalf + 2 * icp + 1)) * 25 + khkw];
    uint16_t h0 = b2u(w0);
    uint16_t h1 = b2u(w1);
    uint16_t l0 = b2u(w0 - u2b(h0));
    uint16_t l1 = b2u(w1 - u2b(h1));
    oH[i] = ((uint32_t)h1 << 16) | h0;
    oL[i] = ((uint32_t)l1 << 16) | l0;
}

// ---------------- cp.async helpers ------------------------------------------
__device__ __forceinline__ void cp4(uint32_t saddr, const void* g, bool ok) {
    int sz = ok ? 4 : 0;
    asm volatile("cp.async.ca.shared.global [%0], [%1], 4, %2;\n"
                 :: "r"(saddr), "l"(g), "r"(sz));
}
__device__ __forceinline__ void cp8(uint32_t saddr, const void* g, bool ok) {
    int sz = ok ? 8 : 0;
    asm volatile("cp.async.ca.shared.global [%0], [%1], 8, %2;\n"
                 :: "r"(saddr), "l"(g), "r"(sz));
}
__device__ __forceinline__ void cpCommit() {
    asm volatile("cp.async.commit_group;\n" ::: "memory");
}
template <int N>
__device__ __forceinline__ void cpWait() {
    asm volatile("cp.async.wait_group %0;\n" :: "n"(N) : "memory");
}
__device__ __forceinline__ void mma16(float* d, uint32_t a0, uint32_t a1, uint32_t a2,
                                      uint32_t a3, uint32_t b0, uint32_t b1) {
    asm volatile(
        "mma.sync.aligned.m16n8k16.row.col.f32.bf16.bf16.f32 "
        "{%0,%1,%2,%3}, {%4,%5,%6,%7}, {%8,%9}, {%0,%1,%2,%3};"
        : "+f"(d[0]), "+f"(d[1]), "+f"(d[2]), "+f"(d[3])
        : "r"(a0), "r"(a1), "r"(a2), "r"(a3), "r"(b0), "r"(b1));
}

// ---------------------------------------------------------------------------
// Strided conv k4 s2 p1, batched over T. Output written H/L uint4 plane format.
// OC = 16: each thread writes 4 complete uint4 plane entries.
// ---------------------------------------------------------------------------
template <int TX, int TY, int OC>
__global__ void conv4s2(const float* __restrict__ in,
                        long long strideB, long long strideT,
                        const float* __restrict__ w, const float* __restrict__ bias,
                        uint4* __restrict__ out,
                        int Cin, int Cout, int Hin, int Win)
{
    const int Hout = Hin >> 1, Wout = Win >> 1;
    const int ocG = Cout / OC;
    int z = blockIdx.z;
    const int ocb = z % ocG; z /= ocG;
    const int b   = z % BATCH;
    const int t   = z / BATCH;
    const int y0  = blockIdx.y * TY;
    const int x0  = blockIdx.x * TX;

    constexpr int IW = 2 * TX + 2;
    constexpr int IH = 2 * TY + 2;
    __shared__ float s_in[IH * IW];
    __shared__ float s_w[OC * 16];

    const int tid = threadIdx.y * TX + threadIdx.x;
    const int nth = TX * TY;
    const float* base = in + (long long)b * strideB + (long long)t * strideT;

    float acc[OC];
#pragma unroll
    for (int oc = 0; oc < OC; oc++) acc[oc] = 0.0f;

    for (int ic = 0; ic < Cin; ic++) {
        const float* src = base + (long long)ic * Hin * Win;
        for (int idx = tid; idx < IH * IW; idx += nth) {
            int iy = 2 * y0 - 1 + idx / IW;
            int ix = 2 * x0 - 1 + idx % IW;
            s_in[idx] = (iy >= 0 && iy < Hin && ix >= 0 && ix < Win)
                            ? src[(long long)iy * Win + ix] : 0.0f;
        }
        for (int idx = tid; idx < OC * 16; idx += nth) {
            int oc = idx / 16, k = idx % 16;
            s_w[idx] = w[(((long long)(ocb * OC + oc)) * Cin + ic) * 16 + k];
        }
        __syncthreads();
#pragma unroll
        for (int kh = 0; kh < 4; kh++)
#pragma unroll
            for (int kw = 0; kw < 4; kw++) {
                float inv = s_in[(2 * threadIdx.y + kh) * IW + 2 * threadIdx.x + kw];
#pragma unroll
                for (int oc = 0; oc < OC; oc++)
                    acc[oc] = fmaf(inv, s_w[oc * 16 + kh * 4 + kw], acc[oc]);
            }
        __syncthreads();
    }

    const int y = y0 + threadIdx.y, x = x0 + threadIdx.x;
    const long long HWo = (long long)Hout * Wout;
    uint4* ob = out + (long long)(t * BATCH + b) * (Cout >> 2) * HWo;
#pragma unroll
    for (int p = 0; p < 4; p++) {
        float v0 = acc[2 * p]         + bias[ocb * 16 + 2 * p];
        float v1 = acc[2 * p + 1]     + bias[ocb * 16 + 2 * p + 1];
        float v2 = acc[8 + 2 * p]     + bias[ocb * 16 + 8 + 2 * p];
        float v3 = acc[8 + 2 * p + 1] + bias[ocb * 16 + 8 + 2 * p + 1];
        uint16_t h0 = b2u(v0), h1 = b2u(v1), h2 = b2u(v2), h3 = b2u(v3);
        uint16_t l0 = b2u(v0 - u2b(h0));
        uint16_t l1 = b2u(v1 - u2b(h1));
        uint16_t l2 = b2u(v2 - u2b(h2));
        uint16_t l3 = b2u(v3 - u2b(h3));
        ob[(long long)(ocb * 4 + p) * HWo + (long long)y * Wout + x]
            = make_uint4(((uint32_t)h1 << 16) | h0, ((uint32_t)h3 << 16) | h2,
                         ((uint32_t)l1 << 16) | l0, ((uint32_t)l3 << 16) | l2);
    }
}

// ---------------------------------------------------------------------------
// 5x5 conv s1 p2, implicit GEMM, bf16 mma.sync.m16n8k16, 3-MMA SINGLE-ACC:
//   acc += wH*bH;  acc += wL*bH;  acc += wH*bL   (all scale 1; only wL*bL ~2^-16
//   dropped). K=16 REAL input channels per trio. Block 128 thr, 16 oc, TX x 8 px.
// smem: input [2buf][4H + 4L planes][SPAD] uint2; weights [2buf][25][2HL][16oc][8].
// EPI 0: fused sigmoid -> zr fp32 + rh split (KS must be 1). EPI 2: raw partial.
// blockIdx.z = ((b*ocG + ocb)*KS + ks)
// ---------------------------------------------------------------------------
template <int TX, int EPI>
__global__ void __launch_bounds__(128)
conv5b3(const uint4* __restrict__ src0, int C0,
        const uint4* __restrict__ src1, int C1,
        const uint32_t* __restrict__ wH, const uint32_t* __restrict__ wL,
        const float* __restrict__ bias,
        float* __restrict__ out, uint4* __restrict__ rhOut,
        int Cout, int H, int W, int ocG, int KS, int chunkIC)
{
    constexpr int TY = 8, IW = TX + 4, IH = TY + 4, IN = IH * IW;
    constexpr int SPAD = IN + ((4 - (IN % 16) + 16) % 16);  // SPAD % 16 == 4
    constexpr int PB = TX / 8;
    constexpr int NG = 2 * PB;
    constexpr int WN = 25 * 256;                             // 6400 u32 per buf

    extern __shared__ uint32_t smu[];
    uint2*    s_in = (uint2*)smu;          // [2][8][SPAD] uint2 (planes 0-3 H, 4-7 L)
    uint32_t* s_w  = smu + 32 * SPAD;      // [2][WN]

    int z = blockIdx.z;
    const int ks  = z % KS;  z /= KS;
    const int ocb = z % ocG;
    const int b   = z / ocG;
    const int y0  = blockIdx.y * TY;
    const int x0  = blockIdx.x * TX;
    const int tid  = threadIdx.x;
    const int warp = tid >> 5, lane = tid & 31;
    const int gid  = lane >> 2, tig = lane & 3;

    const int Cin = C0 + C1;
    const long long HW = (long long)H * W;
    const int icBeg = ks * chunkIC;
    const int NC = chunkIC / 16;            // 16 real channels per chunk

    const uint32_t sIN = (uint32_t)__cvta_generic_to_shared(s_in);
    const uint32_t sWB = (uint32_t)__cvta_generic_to_shared(s_w);

    auto fillChunk = [&](int buf, int ck) {
        const int cs = icBeg + ck * 16;  // chunks never straddle the C0 boundary
        const uint4* pb = (cs < C0)
            ? src0 + ((long long)b * (C0 >> 2) + (cs >> 2)) * HW
            : src1 + ((long long)b * (C1 >> 2) + ((cs - C0) >> 2)) * HW;
        for (int idx = tid; idx < IN; idx += 128) {
            int rr = idx / IW, cc = idx - rr * IW;
            int iy = y0 - 2 + rr, ix = x0 - 2 + cc;
            bool ok = (iy >= 0) && (iy < H) && (ix >= 0) && (ix < W);
            const uint4* g = ok ? (pb + (long long)iy * W + ix) : pb;
            uint32_t dH = sIN + (uint32_t)(buf * 8 * SPAD + idx) * 8u;
            uint32_t dL = dH + (uint32_t)(4 * SPAD) * 8u;
#pragma unroll
            for (int t = 0; t < 4; t++) {
                const char* gp = (const char*)(g + (long long)t * HW);
                cp8(dH + (uint32_t)(t * SPAD) * 8u, gp, ok);       // H pair
                cp8(dL + (uint32_t)(t * SPAD) * 8u, gp + 8, ok);   // L pair
            }
        }
        for (int idx = tid; idx < WN; idx += 128) {
            // idx = khkw*256 + half*128 + oc*8 + e ; e=2p+j -> kpair = p + 4j
            int khkw = idx >> 8;
            int rem  = idx & 255;
            int half = rem >> 7;
            int r2   = rem & 127;
            int oc   = r2 >> 3;
            int e    = r2 & 7;
            int kp   = (e >> 1) + 4 * (e & 1);
            int icp  = (cs >> 1) + kp;
            const uint32_t* g = (half ? wL : wH)
                + ((long long)(ocb * 16 + oc) * (Cin >> 1) + icp) * 25 + khkw;
            cp4(sWB + (uint32_t)(buf * WN + idx) * 4u, g, true);
        }
    };

    float acc[NG][4];
#pragma unroll
    for (int g = 0; g < NG; g++)
#pragma unroll
        for (int j = 0; j < 4; j++) acc[g][j] = 0.0f;

    fillChunk(0, 0);
    cpCommit();

    for (int ck = 0; ck < NC; ck++) {
        const int cur = ck & 1;
        if (ck + 1 < NC) fillChunk(cur ^ 1, ck + 1);
        cpCommit();
        cpWait<1>();
        __syncthreads();

        const uint2*    siTH = s_in + cur * 8 * SPAD + tig * SPAD;
        const uint2*    siTL = siTH + 4 * SPAD;
        const uint32_t* swB  = s_w + cur * WN;
        const int prow = 2 * warp;

#pragma unroll
        for (int kh = 0; kh < 5; kh++) {
#pragma unroll
            for (int kw = 0; kw < 5; kw++) {
                const uint32_t* swk = swB + (kh * 5 + kw) * 256;
                uint2 h02 = *(const uint2*)(swk + gid * 8 + tig * 2);
                uint2 h13 = *(const uint2*)(swk + (gid + 8) * 8 + tig * 2);
                uint2 l02 = *(const uint2*)(swk + 128 + gid * 8 + tig * 2);
                uint2 l13 = *(const uint2*)(swk + 128 + (gid + 8) * 8 + tig * 2);
#pragma unroll
                for (int g = 0; g < NG; g++) {
                    const int r = g / PB, pb2 = g % PB;
                    const int px = (prow + r + kh) * IW + 8 * pb2 + gid + kw;
                    uint2 bH = siTH[px];
                    uint2 bL = siTL[px];
                    mma16(acc[g], h02.x, h13.x, h02.y, h13.y, bH.x, bH.y);
                    mma16(acc[g], l02.x, l13.x, l02.y, l13.y, bH.x, bH.y);
                    mma16(acc[g], h02.x, h13.x, h02.y, h13.y, bL.x, bL.y);
                }
            }
        }
        __syncthreads();
    }

    // epilogue
#pragma unroll
    for (int g = 0; g < NG; g++) {
        const int r = g / PB, pb2 = g % PB;
        const int y = y0 + 2 * warp + r;
        const int xb = x0 + 8 * pb2 + 2 * tig;
#pragma unroll
        for (int j = 0; j < 4; j++) {
            const int m = gid + ((j >> 1) << 3);
            const int x = xb + (j & 1);
            const int c = ocb * 16 + m;
            const long long pix = (long long)y * W + x;
            float v = acc[g][j];
            if (EPI == 0) {
                float a = v + bias[c];
                float s = 1.0f / (1.0f + expf(-a));
                out[((long long)b * Cout + c) * HW + pix] = s;
                const int Ch = Cout >> 1;
                if (c >= Ch) {
                    int hc = c - Ch;
                    const uint4* hp = src1 + (long long)b * (C1 >> 2) * HW;
                    float hv = loadSplit(hp, hc, HW, pix);
                    uint4* rp = rhOut + (long long)b * (C1 >> 2) * HW;
                    storeSplit(rp, hc, HW, pix, s * hv);
                }
            } else {
                out[((long long)(ks * BATCH + b) * Cout + c) * HW + pix] = v;
            }
        }
    }
}

// ---------------------------------------------------------------------------
// Split-K epilogues
// ---------------------------------------------------------------------------
__global__ void zrEpiK(const float* __restrict__ part, int KS,
                       const float* __restrict__ bias, const float* __restrict__ hprevFp,
                       float* __restrict__ zrOut, uint4* __restrict__ rhSp,
                       int C2, long long HW)
{
    const long long n = (long long)BATCH * C2 * HW;
    long long i = (long long)blockIdx.x * blockDim.x + threadIdx.x;
    if (i >= n) return;
    float s = 0.0f;
    for (int k = 0; k < KS; k++) s += part[(long long)k * n + i];
    const int c = (int)((i / HW) % C2);
    s += bias[c];
    float sg = 1.0f / (1.0f + expf(-s));
    zrOut[i] = sg;
    const int C = C2 >> 1;
    if (c >= C) {
        long long b = i / (HW * C2);
        long long pix = i % HW;
        int hc = c - C;
        float rv = sg * hprevFp[(b * C + hc) * HW + pix];
        storeSplit(rhSp + b * (C >> 2) * HW, hc, HW, pix, rv);
    }
}

__global__ void hEpiK(const float* __restrict__ part, int KS,
                      const float* __restrict__ bias, const float* __restrict__ zr,
                      const float* __restrict__ hprevFp,
                      float* __restrict__ outFp, uint4* __restrict__ outSp,
                      int C, long long HW)
{
    const long long n = (long long)BATCH * C * HW;
    long long i = (long long)blockIdx.x * blockDim.x + threadIdx.x;
    if (i >= n) return;
    float s = 0.0f;
    for (int k = 0; k < KS; k++) s += part[(long long)k * n + i];
    const int c = (int)((i / HW) % C);
    long long b = i / (HW * C);
    long long pix = i % HW;
    float a = s + bias[c];
    float zv = zr[(b * (2 * C) + c) * HW + pix];
    float hp = hprevFp[i];
    float res = (1.0f - zv) * hp + zv * tanhf(a);
    outFp[i] = res;
    storeSplit(outSp + b * (C >> 2) * HW, c, HW, pix, res);
}

// ---------------------------------------------------------------------------

extern "C" void kernel_launch(void* const* d_in, const int* in_sizes, int n_in,
                              void* d_out, int out_size)
{
    const float* input   = (const float*)d_in[0];
    const float* c1_w    = (const float*)d_in[1];
    const float* c1_b    = (const float*)d_in[2];
    const float* g1_zr_w = (const float*)d_in[3];
    const float* g1_zr_b = (const float*)d_in[4];
    const float* g1_h_w  = (const float*)d_in[5];
    const float* g1_h_b  = (const float*)d_in[6];
    const float* c2_w    = (const float*)d_in[7];
    const float* c2_b    = (const float*)d_in[8];
    const float* g2_zr_w = (const float*)d_in[9];
    const float* g2_zr_b = (const float*)d_in[10];
    const float* g2_h_w  = (const float*)d_in[11];
    const float* g2_h_b  = (const float*)d_in[12];
    const float* c3_w    = (const float*)d_in[13];
    const float* c3_b    = (const float*)d_in[14];
    const float* g3_zr_w = (const float*)d_in[15];
    const float* g3_zr_b = (const float*)d_in[16];
    const float* g3_h_w  = (const float*)d_in[17];
    const float* g3_h_b  = (const float*)d_in[18];

    float *seq1, *seq2, *h3a, *h3b, *zr, *part, *zero0;
    uint4 *xsp1, *xsp2, *xsp3, *hsp1a, *hsp1b, *hsp2a, *hsp2b, *hsp3a, *hsp3b, *rhsp, *zsp;
    uint32_t* wc;
    cudaGetSymbolAddress((void**)&seq1,  g_seq1);
    cudaGetSymbolAddress((void**)&seq2,  g_seq2);
    cudaGetSymbolAddress((void**)&h3a,   g_h3a);
    cudaGetSymbolAddress((void**)&h3b,   g_h3b);
    cudaGetSymbolAddress((void**)&xsp1,  g_xsp1);
    cudaGetSymbolAddress((void**)&xsp2,  g_xsp2);
    cudaGetSymbolAddress((void**)&xsp3,  g_xsp3);
    cudaGetSymbolAddress((void**)&hsp1a, g_hsp1a);
    cudaGetSymbolAddress((void**)&hsp1b, g_hsp1b);
    cudaGetSymbolAddress((void**)&hsp2a, g_hsp2a);
    cudaGetSymbolAddress((void**)&hsp2b, g_hsp2b);
    cudaGetSymbolAddress((void**)&hsp3a, g_hsp3a);
    cudaGetSymbolAddress((void**)&hsp3b, g_hsp3b);
    cudaGetSymbolAddress((void**)&rhsp,  g_rhsp);
    cudaGetSymbolAddress((void**)&zr,    g_zr);
    cudaGetSymbolAddress((void**)&part,  g_part);
    cudaGetSymbolAddress((void**)&zero0, g_zero);
    cudaGetSymbolAddress((void**)&zsp,   g_zsp);
    cudaGetSymbolAddress((void**)&wc,    g_wcvt);

    // converted-weight offsets: per conv, H then L (each Noc*Cin/2*25 words)
    uint32_t* w1zrH = wc;                  // 128*64*25  = 204800
    uint32_t* w1zrL = wc + 204800;
    uint32_t* w1hH  = wc + 409600;         //  64*64*25  = 102400
    uint32_t* w1hL  = wc + 512000;
    uint32_t* w2zrH = wc + 614400;         // 256*128*25 = 819200
    uint32_t* w2zrL = wc + 1433600;
    uint32_t* w2hH  = wc + 2252800;        // 128*128*25 = 409600
    uint32_t* w2hL  = wc + 2662400;
    uint32_t* w3zrH = wc + 3072000;        // 819200
    uint32_t* w3zrL = wc + 3891200;
    uint32_t* w3hH  = wc + 4710400;        // 409600
    uint32_t* w3hL  = wc + 5120000;

    // smem sizes: input [2][8][SPAD] uint2 + weights [2][6400] u32
    constexpr int IN32 = 12 * 36, SP32 = IN32 + ((4 - (IN32 % 16) + 16) % 16); // 436
    constexpr int IN16 = 12 * 20, SP16 = IN16 + ((4 - (IN16 % 16) + 16) % 16); // 244
    constexpr int WN2  = 2 * 25 * 256;                                          // 12800 u32
    constexpr int SM32 = (32 * SP32 + WN2) * 4;   // 107,008 B -> 2 blocks/SM
    constexpr int SM16 = (32 * SP16 + WN2) * 4;   //  82,432 B -> 2 blocks/SM
    cudaFuncSetAttribute(conv5b3<32, 0>, cudaFuncAttributeMaxDynamicSharedMemorySize, SM32);
    cudaFuncSetAttribute(conv5b3<32, 2>, cudaFuncAttributeMaxDynamicSharedMemorySize, SM32);
    cudaFuncSetAttribute(conv5b3<16, 2>, cudaFuncAttributeMaxDynamicSharedMemorySize, SM16);

    {   // zero h0 buffers (fp32 + uint4 planes)
        int nz = BATCH * 64 * 64 * 64;
        int nz2 = BATCH * 16 * 64 * 64;
        zerok<<<(nz + 255) / 256, 256>>>(zero0, zsp, nz, nz2);
    }

    const size_t S1  = (size_t)BATCH * 64 * 64 * 64;
    const size_t S2  = (size_t)BATCH * 128 * 32 * 32;
    const size_t S1p = (size_t)BATCH * 16 * 64 * 64;
    const size_t S2p = (size_t)BATCH * 32 * 32 * 32;
    const size_t S3p = (size_t)BATCH * 32 * 16 * 16;

    // ================= Stage 1: 1 -> 64ch, 128x128 -> 64x64 =================
    conv4s2<16, 8, 16><<<dim3(4, 8, TSTEPS * BATCH * 4), dim3(16, 8)>>>(
        input, (long long)TSTEPS * 128 * 128, (long long)128 * 128,
        c1_w, c1_b, xsp1, 1, 64, 128, 128);

    wcvt2K<<<(204800 + 255) / 256, 256>>>(g1_zr_w, w1zrH, w1zrL, 204800, 64);
    wcvt2K<<<(102400 + 255) / 256, 256>>>(g1_h_w,  w1hH,  w1hL,  102400, 64);

    {
        uint4* hspb[2] = { hsp1a, hsp1b };
        for (int t = 0; t < TSTEPS; t++) {
            const uint4* xt = xsp1 + (size_t)t * S1p;
            const uint4* hprevSp = t ? hspb[(t - 1) & 1] : zsp;
            const float* hprevFp = t ? seq1 + (size_t)(t - 1) * S1 : zero0;
            // zr fused (KS=1): Cout=128, ocG=8
            conv5b3<32, 0><<<dim3(2, 8, BATCH * 8), 128, SM32>>>(
                xt, 64, hprevSp, 64, w1zrH, w1zrL, g1_zr_b, zr, rhsp, 128, 64, 64, 8, 1, 128);
            // h raw split-K=2: Cout=64, ocG=4
            conv5b3<32, 2><<<dim3(2, 8, BATCH * 4 * 2), 128, SM32>>>(
                xt, 64, rhsp, 64, w1hH, w1hL, nullptr, part, nullptr, 64, 64, 64, 4, 2, 64);
            long long n = (long long)BATCH * 64 * 4096;
            hEpiK<<<(unsigned)((n + 255) / 256), 256>>>(
                part, 2, g1_h_b, zr, hprevFp, seq1 + (size_t)t * S1, hspb[t & 1], 64, 4096);
        }
    }

    // stage-2/3 weight conversions (needed before stage 2)
    wcvt2K<<<(819200 + 255) / 256, 256>>>(g2_zr_w, w2zrH, w2zrL, 819200, 128);
    wcvt2K<<<(409600 + 255) / 256, 256>>>(g2_h_w,  w2hH,  w2hL,  409600, 128);
    wcvt2K<<<(819200 + 255) / 256, 256>>>(g3_zr_w, w3zrH, w3zrL, 819200, 128);
    wcvt2K<<<(409600 + 255) / 256, 256>>>(g3_h_w,  w3hH,  w3hL,  409600, 128);

    // ================= Stage 2: 64 -> 128ch, 64x64 -> 32x32 =================
    conv4s2<16, 8, 16><<<dim3(2, 4, TSTEPS * BATCH * 8), dim3(16, 8)>>>(
        seq1, (long long)64 * 4096, (long long)BATCH * 64 * 4096,
        c2_w, c2_b, xsp2, 64, 128, 64, 64);

    {
        uint4* hspb[2] = { hsp2a, hsp2b };
        for (int t = 0; t < TSTEPS; t++) {
            const uint4* xt = xsp2 + (size_t)t * S2p;
            const uint4* hprevSp = t ? hspb[(t - 1) & 1] : zsp;
            const float* hprevFp = t ? seq2 + (size_t)(t - 1) * S2 : zero0;
            // zr raw split-K=2: Cout=256, ocG=16
            conv5b3<32, 2><<<dim3(1, 4, BATCH * 16 * 2), 128, SM32>>>(
                xt, 128, hprevSp, 128, w2zrH, w2zrL, nullptr, part, nullptr, 256, 32, 32, 16, 2, 128);
            {
                long long n = (long long)BATCH * 256 * 1024;
                zrEpiK<<<(unsigned)((n + 255) / 256), 256>>>(part, 2, g2_zr_b, hprevFp, zr, rhsp, 256, 1024);
            }
            // h raw split-K=4: Cout=128, ocG=8
            conv5b3<32, 2><<<dim3(1, 4, BATCH * 8 * 4), 128, SM32>>>(
                xt, 128, rhsp, 128, w2hH, w2hL, nullptr, part, nullptr, 128, 32, 32, 8, 4, 64);
            long long n = (long long)BATCH * 128 * 1024;
            hEpiK<<<(unsigned)((n + 255) / 256), 256>>>(
                part, 4, g2_h_b, zr, hprevFp, seq2 + (size_t)t * S2, hspb[t & 1], 128, 1024);
        }
    }

    // ================= Stage 3: 128 -> 128ch, 32x32 -> 16x16 ================
    conv4s2<16, 8, 16><<<dim3(1, 2, TSTEPS * BATCH * 8), dim3(16, 8)>>>(
        seq2, (long long)128 * 1024, (long long)BATCH * 128 * 1024,
        c3_w, c3_b, xsp3, 128, 128, 32, 32);

    float* h3final = nullptr;
    {
        uint4* hspb[2] = { hsp3a, hsp3b };
        float* hfp[2]  = { h3a, h3b };
        for (int t = 0; t < TSTEPS; t++) {
            const uint4* xt = xsp3 + (size_t)t * S3p;
            const uint4* hprevSp = t ? hspb[(t - 1) & 1] : zsp;
            const float* hprevFp = t ? hfp[(t - 1) & 1] : zero0;
            // zr raw split-K=4: Cout=256, ocG=16
            conv5b3<16, 2><<<dim3(1, 2, BATCH * 16 * 4), 128, SM16>>>(
                xt, 128, hprevSp, 128, w3zrH, w3zrL, nullptr, part, nullptr, 256, 16, 16, 16, 4, 64);
            {
                long long n = (long long)BATCH * 256 * 256;
                zrEpiK<<<(unsigned)((n + 255) / 256), 256>>>(part, 4, g3_zr_b, hprevFp, zr, rhsp, 256, 256);
            }
            // h raw split-K=8: Cout=128, ocG=8
            conv5b3<16, 2><<<dim3(1, 2, BATCH * 8 * 8), 128, SM16>>>(
                xt, 128, rhsp, 128, w3hH, w3hL, nullptr, part, nullptr, 128, 16, 16, 8, 8, 32);
            long long n = (long long)BATCH * 128 * 256;
            hEpiK<<<(unsigned)((n + 255) / 256), 256>>>(
                part, 8, g3_h_b, zr, hprevFp, hfp[t & 1], hspb[t & 1], 128, 256);
            h3final = hfp[t & 1];
        }
    }

    // ================= Gather outputs =================
    float* out = (float*)d_out;
    int n1 = (int)S1, n2 = (int)S2, n3 = BATCH * 128 * 16 * 16;
    copyk<<<(n1 + 255) / 256, 256>>>(out, seq1 + (size_t)(TSTEPS - 1) * S1, n1);
    copyk<<<(n2 + 255) / 256, 256>>>(out + n1, seq2 + (size_t)(TSTEPS - 1) * S2, n2);
    copyk<<<(n3 + 255) / 256, 256>>>(out + n1 + n2, h3final, n3);
}